// round 11
// baseline (speedup 1.0000x reference)
#include <cuda_runtime.h>
#include <cstdint>

#define BEV_H 128
#define BEV_W 128
#define HW_ (BEV_H * BEV_W)
#define NBKT (4 * HW_)            // 65536 buckets
#define C_MID 80
#define C_OUT 128
#define B_ 4
#define NP_ 200000
#define TOTAL_PTS (B_ * NP_)
#define INVALID_G 0xFFFFFFFFu

#define MLP_CTAS 1184
#define MLP_WARPS (MLP_CTAS * 4)

#define BEV_TILES (B_ * HW_ / 16)
#define BEV_TPW 4
#define BEV_GRID (BEV_TILES / (4 * BEV_TPW))   // 256

// Scratch (device globals; zero-init at load, re-zeroed per launch as noted).
__device__ float g_sums[(size_t)B_ * HW_ * C_MID];  // zeroed by bev kernel
__device__ int h_cnt[NBKT];                          // zeroed by zero kernel
__device__ int g_off[NBKT + 1];                      // fully rewritten by scan
__device__ unsigned g_bkt[TOTAL_PTS];                // fully rewritten by pass A
__device__ unsigned g_ids[TOTAL_PTS];                // written by pass B (valid prefix)

// ---------------------------------------------------------------------------
// helpers
// ---------------------------------------------------------------------------
__device__ __forceinline__ uint32_t f2tf32(float x) {
    uint32_t u;
    asm("cvt.rna.tf32.f32 %0, %1;" : "=r"(u) : "f"(x));
    return u;
}
__device__ __forceinline__ uint32_t packh2(float lo, float hi) {
    uint32_t r;
    asm("cvt.rn.f16x2.f32 %0, %1, %2;" : "=r"(r) : "f"(hi), "f"(lo));
    return r;
}
__device__ __forceinline__ void mma_f16(float* c, const uint32_t* a,
                                        uint32_t b0, uint32_t b1) {
    asm("mma.sync.aligned.m16n8k16.row.col.f32.f16.f16.f32 "
        "{%0,%1,%2,%3}, {%4,%5,%6,%7}, {%8,%9}, {%0,%1,%2,%3};"
        : "+f"(c[0]), "+f"(c[1]), "+f"(c[2]), "+f"(c[3])
        : "r"(a[0]), "r"(a[1]), "r"(a[2]), "r"(a[3]), "r"(b0), "r"(b1));
}
__device__ __forceinline__ void mma_tf32(float* c, const uint32_t* a,
                                         uint32_t b0, uint32_t b1) {
    asm("mma.sync.aligned.m16n8k8.row.col.f32.tf32.tf32.f32 "
        "{%0,%1,%2,%3}, {%4,%5,%6,%7}, {%8,%9}, {%0,%1,%2,%3};"
        : "+f"(c[0]), "+f"(c[1]), "+f"(c[2]), "+f"(c[3])
        : "r"(a[0]), "r"(a[1]), "r"(a[2]), "r"(a[3]), "r"(b0), "r"(b1));
}
__device__ __forceinline__ void red_v4(float* addr, float4 v) {
    asm volatile("red.global.add.v4.f32 [%0], {%1, %2, %3, %4};"
                 :: "l"(addr), "f"(v.x), "f"(v.y), "f"(v.z), "f"(v.w) : "memory");
}

// ---------------------------------------------------------------------------
// Pipeline kernels
// ---------------------------------------------------------------------------
__global__ void zero_hist_kernel() {
    int i = blockIdx.x * 256 + threadIdx.x;
    if (i < NBKT) h_cnt[i] = 0;
}

__global__ __launch_bounds__(256)
void pass_a_kernel(const float4* __restrict__ pts) {
    int i = blockIdx.x * 256 + threadIdx.x;
    float4 p = pts[i];
    int ix = (int)floorf((p.x + 50.0f) / 0.78125f);
    int iy = (int)floorf((p.y + 50.0f) / 0.78125f);
    bool v = (ix >= 0) & (ix < BEV_W) & (iy >= 0) & (iy < BEV_H);
    unsigned g = v ? (unsigned)((i / NP_) * HW_ + iy * BEV_W + ix) : INVALID_G;
    g_bkt[i] = g;
    if (v) atomicAdd(&h_cnt[g], 1);
}

__global__ __launch_bounds__(1024)
void scan_kernel() {
    __shared__ int ssum[1024];
    const int t = threadIdx.x;
    const int base = t * (NBKT / 1024);   // 64 per thread
    int run = 0;
#pragma unroll 8
    for (int k = 0; k < NBKT / 1024; k++) run += h_cnt[base + k];
    ssum[t] = run;
    __syncthreads();
    int x = run;
    for (int d = 1; d < 1024; d <<= 1) {
        int y = (t >= d) ? ssum[t - d] : 0;
        __syncthreads();
        x += y;
        ssum[t] = x;
        __syncthreads();
    }
    int excl = x - run;
    int acc = excl;
#pragma unroll 8
    for (int k = 0; k < NBKT / 1024; k++) {
        int c = h_cnt[base + k];
        g_off[base + k] = acc;
        acc += c;
    }
    if (t == 1023) g_off[NBKT] = x;   // total valid points
}

__global__ __launch_bounds__(256)
void pass_b_kernel() {
    int i = blockIdx.x * 256 + threadIdx.x;
    unsigned g = g_bkt[i];
    if (g != INVALID_G) {
        int pos = atomicAdd(&g_off[g], 1);
        g_ids[pos] = (unsigned)i;
    }
}

// ---------------------------------------------------------------------------
// MLP kernel: sorted points, both layers on tensor cores, segmented scatter.
// ---------------------------------------------------------------------------
#define SM_W2F   0            // 12800 B
#define SM_W1F   12800        // 2560 B
#define SM_B2    15360        // 320 B
#define SM_SBKT  15680        // 512 B (4 warps * 32 int)
#define SM_BUF   16192        // 40960 B (4 warps * 32*80 f32)
#define SM_TOTAL 57152

__global__ __launch_bounds__(128, 4)
void point_mma_kernel(const float4* __restrict__ pts,
                      const float* __restrict__ W1, const float* __restrict__ b1,
                      const float* __restrict__ W2, const float* __restrict__ b2) {
    extern __shared__ __align__(16) char smem[];
    uint32_t* sW2F = (uint32_t*)(smem + SM_W2F);
    uint32_t* sW1F = (uint32_t*)(smem + SM_W1F);
    float*    sb2  = (float*)(smem + SM_B2);
    int*      sbktA = (int*)(smem + SM_SBKT);

    const int tid = threadIdx.x;
    const int w = tid >> 5;
    const int lane = tid & 31;
    const int qg = lane >> 2;
    const int tig = lane & 3;
    int*   sbkt = sbktA + w * 32;
    float* buf  = (float*)(smem + SM_BUF) + w * 32 * C_MID;

    for (int i = tid; i < C_MID; i += 128) sb2[i] = b2[i];
    for (int e = tid; e < 3200; e += 128) {
        int reg = e & 1;
        int L = (e >> 1) & 31;
        int idx = e >> 6;
        int ns = idx % 10, ks = idx / 10;
        int k0 = ks * 16 + 2 * (L & 3) + reg * 8;
        int n = ns * 8 + (L >> 2);
        sW2F[e] = packh2(W2[k0 * C_MID + n], W2[(k0 + 1) * C_MID + n]);
    }
    for (int e = tid; e < 640; e += 128) {
        int pair = e & 1;
        int L = (e >> 1) & 31;
        int ns = e >> 6;
        int tg = L & 3;
        int n = ns * 8 + (L >> 2);
        float v;
        if (pair == 0) v = W1[tg * C_MID + n];
        else           v = (tg == 0) ? b1[n] : W1[(tg - 1) * C_MID + n];
        sW1F[e] = f2tf32(v);
    }
    __syncthreads();

    float4 bias4 = make_float4(0.f, 0.f, 0.f, 0.f);
    if (lane < 20) bias4 = *reinterpret_cast<const float4*>(&sb2[4 * lane]);

    const int valid = g_off[NBKT];
    const int ntiles = (valid + 31) >> 5;
    const int gwarp = blockIdx.x * 4 + w;

#pragma unroll 1
    for (int tile = gwarp; tile < ntiles; tile += MLP_WARPS) {
        const int base = tile * 32;

        // Gather 4 sorted rows (qg + 8j); quad-broadcast.
        float4 P[4];
        int ids[4];
        bool vr[4];
#pragma unroll
        for (int j = 0; j < 4; j++) {
            int r = base + qg + 8 * j;
            bool ok = r < valid;
            int id = ok ? (int)g_ids[r] : 0;
            ids[j] = id; vr[j] = ok;
            P[j] = pts[id];
        }

        // Owned row (qg + 8*tig): recompute bucket, publish to sbkt.
        {
            int myg = -1;
            if (vr[tig]) {
                float4 po = P[tig];
                int ixo = (int)floorf((po.x + 50.0f) / 0.78125f);
                int iyo = (int)floorf((po.y + 50.0f) / 0.78125f);
                myg = (ids[tig] / NP_) * HW_ + iyo * BEV_W + ixo;
            }
            sbkt[qg + 8 * tig] = myg;
        }
        __syncwarp();

        // Layer-1 A fragments (split tf32, exact).
        uint32_t ALo[4], AHi[4];
#pragma unroll
        for (int j = 0; j < 4; j++) {
            float4 p = P[j];
            float ch = (tig == 0) ? p.x : (tig == 1) ? p.y : (tig == 2) ? p.z : p.w;
            uint32_t ahi = f2tf32(ch);
            float cl = (tig == 1) ? p.x : (tig == 2) ? p.y : p.z;
            float lo = cl - __uint_as_float(f2tf32(cl));
            uint32_t alo = (tig == 0) ? 0x3f800000u : f2tf32(lo);
            if (j < 2) { ALo[j] = ahi; ALo[2 + j] = alo; }
            else       { AHi[j - 2] = ahi; AHi[j] = alo; }
        }

        // Layer 1 via mma -> fp16 layer-2 A fragments.
        uint32_t A0[5][4], A1[5][4];
#pragma unroll
        for (int ns = 0; ns < 10; ns++) {
            uint2 bf = *reinterpret_cast<const uint2*>(&sW1F[(ns * 32 + lane) * 2]);
            float cL[4] = {0.f, 0.f, 0.f, 0.f};
            float cH[4] = {0.f, 0.f, 0.f, 0.f};
            mma_tf32(cL, ALo, bf.x, bf.y);
            mma_tf32(cH, AHi, bf.x, bf.y);
            const int ks = ns >> 1, sub = ns & 1;
            A0[ks][2 * sub + 0] = packh2(fmaxf(cL[0], 0.f), fmaxf(cL[1], 0.f));
            A0[ks][2 * sub + 1] = packh2(fmaxf(cL[2], 0.f), fmaxf(cL[3], 0.f));
            A1[ks][2 * sub + 0] = packh2(fmaxf(cH[0], 0.f), fmaxf(cH[1], 0.f));
            A1[ks][2 * sub + 1] = packh2(fmaxf(cH[2], 0.f), fmaxf(cH[3], 0.f));
        }

        // Layer 2: stage raw mma outputs to smem (row-major, stride 80).
#pragma unroll 1
        for (int ns = 0; ns < 10; ns++) {
            float c0[4] = {0.f, 0.f, 0.f, 0.f};
            float c1[4] = {0.f, 0.f, 0.f, 0.f};
#pragma unroll
            for (int ks = 0; ks < 5; ks++) {
                uint2 bf = *reinterpret_cast<const uint2*>(
                    &sW2F[((ks * 10 + ns) * 32 + lane) * 2]);
                mma_f16(c0, A0[ks], bf.x, bf.y);
                mma_f16(c1, A1[ks], bf.x, bf.y);
            }
            const int col = ns * 8 + 2 * tig;
            *reinterpret_cast<float2*>(&buf[qg * C_MID + col])        = make_float2(c0[0], c0[1]);
            *reinterpret_cast<float2*>(&buf[(qg + 8) * C_MID + col])  = make_float2(c0[2], c0[3]);
            *reinterpret_cast<float2*>(&buf[(qg + 16) * C_MID + col]) = make_float2(c1[0], c1[1]);
            *reinterpret_cast<float2*>(&buf[(qg + 24) * C_MID + col]) = make_float2(c1[2], c1[3]);
        }
        __syncwarp();

        // Segmented reduction over sorted rows; one red.v4 per segment.
        // Branches are warp-uniform (bk comes from shared, same for all lanes).
        int cur = -1;
        float4 acc = make_float4(0.f, 0.f, 0.f, 0.f);
#pragma unroll 1
        for (int r = 0; r < 32; r++) {
            int bk = sbkt[r];
            float4 v = make_float4(0.f, 0.f, 0.f, 0.f);
            if (lane < 20) v = *reinterpret_cast<const float4*>(&buf[r * C_MID + 4 * lane]);
            v.x = fmaxf(v.x + bias4.x, 0.0f);
            v.y = fmaxf(v.y + bias4.y, 0.0f);
            v.z = fmaxf(v.z + bias4.z, 0.0f);
            v.w = fmaxf(v.w + bias4.w, 0.0f);
            if (bk != cur) {
                if (cur >= 0 && lane < 20)
                    red_v4(&g_sums[(size_t)cur * C_MID + 4 * lane], acc);
                cur = bk;
                acc = v;
            } else {
                acc.x += v.x; acc.y += v.y; acc.z += v.z; acc.w += v.w;
            }
        }
        if (cur >= 0 && lane < 20)
            red_v4(&g_sums[(size_t)cur * C_MID + 4 * lane], acc);
        __syncwarp();
    }
}

// ---------------------------------------------------------------------------
// bev kernel: mean + 1x1 conv + BN + relu via tensor cores.
// Counts come from h_cnt (int). Zeroes g_sums behind the reads.
// ---------------------------------------------------------------------------
__global__ __launch_bounds__(128)
void bev_mma_kernel(const float* __restrict__ Wp, const float* __restrict__ bp,
                    const float* __restrict__ gamma, const float* __restrict__ beta,
                    const float* __restrict__ rmean, const float* __restrict__ rvar,
                    float* __restrict__ out) {
    __shared__ uint32_t sWpF[10 * 16 * 32 * 2];  // 40 KB
    __shared__ float sScale[C_OUT];
    __shared__ float sShift[C_OUT];

    const int tid = threadIdx.x;
    const int w = tid >> 5;
    const int lane = tid & 31;
    const int qg = lane >> 2;
    const int tig = lane & 3;

    for (int e = tid; e < 10240; e += 128) {
        int pair = e & 1;
        int L = (e >> 1) & 31;
        int idx = e >> 6;
        int ns = idx & 15, ks = idx >> 4;
        int k = ks * 8 + (L & 3) + pair * 4;
        int n = ns * 8 + (L >> 2);
        sWpF[e] = f2tf32(Wp[k * C_OUT + n]);
    }
    if (tid < C_OUT) {
        float sc = gamma[tid] * rsqrtf(rvar[tid] + 1e-5f);
        sScale[tid] = sc;
        sShift[tid] = beta[tid] + (bp[tid] - rmean[tid]) * sc;
    }
    __syncthreads();

#pragma unroll 1
    for (int t = 0; t < BEV_TPW; t++) {
        const int tile = (blockIdx.x * 4 + w) * BEV_TPW + t;
        const int tb = tile * 16;

        float inv0 = 1.0f / fmaxf((float)h_cnt[tb + qg], 1.0f);
        float inv1 = 1.0f / fmaxf((float)h_cnt[tb + qg + 8], 1.0f);
        const float* p0 = &g_sums[(size_t)(tb + qg) * C_MID];
        const float* p1 = &g_sums[(size_t)(tb + qg + 8) * C_MID];

        uint32_t A[10][4];
#pragma unroll
        for (int ks = 0; ks < 10; ks++) {
            const int c0 = ks * 8 + tig, c1 = c0 + 4;
            A[ks][0] = f2tf32(p0[c0] * inv0);
            A[ks][1] = f2tf32(p1[c0] * inv1);
            A[ks][2] = f2tf32(p0[c1] * inv0);
            A[ks][3] = f2tf32(p1[c1] * inv1);
        }
        __syncwarp();
        float4* zs = reinterpret_cast<float4*>(&g_sums[(size_t)tb * C_MID]);
#pragma unroll
        for (int j = 0; j < 10; j++)
            zs[lane + 32 * j] = make_float4(0.f, 0.f, 0.f, 0.f);

        const int b = tb / HW_;
        const int rem = tb % HW_;
        float* outb = out + (size_t)b * C_OUT * HW_ + rem;

#pragma unroll 1
        for (int ns = 0; ns < 16; ns++) {
            float c[4] = {0.f, 0.f, 0.f, 0.f};
#pragma unroll
            for (int ks = 0; ks < 10; ks++) {
                uint2 bf = *reinterpret_cast<const uint2*>(
                    &sWpF[((ks * 16 + ns) * 32 + lane) * 2]);
                mma_tf32(c, A[ks], bf.x, bf.y);
            }
            const int col0 = ns * 8 + 2 * tig;
            float2 sc = *reinterpret_cast<const float2*>(&sScale[col0]);
            float2 sh = *reinterpret_cast<const float2*>(&sShift[col0]);
            outb[(size_t)col0 * HW_ + qg]           = fmaxf(fmaf(c[0], sc.x, sh.x), 0.0f);
            outb[(size_t)(col0 + 1) * HW_ + qg]     = fmaxf(fmaf(c[1], sc.y, sh.y), 0.0f);
            outb[(size_t)col0 * HW_ + qg + 8]       = fmaxf(fmaf(c[2], sc.x, sh.x), 0.0f);
            outb[(size_t)(col0 + 1) * HW_ + qg + 8] = fmaxf(fmaf(c[3], sc.y, sh.y), 0.0f);
        }
        __syncwarp();
    }
}

__global__ void probe_kernel() {}

// ---------------------------------------------------------------------------
extern "C" void kernel_launch(void* const* d_in, const int* in_sizes, int n_in,
                              void* d_out, int out_size) {
    const float4* pts   = (const float4*)d_in[0];
    const float*  W1    = (const float*)d_in[1];
    const float*  b1    = (const float*)d_in[2];
    const float*  W2    = (const float*)d_in[3];
    const float*  b2    = (const float*)d_in[4];
    const float*  Wp    = (const float*)d_in[5];
    const float*  bp    = (const float*)d_in[6];
    const float*  gamma = (const float*)d_in[7];
    const float*  beta  = (const float*)d_in[8];
    const float*  rmean = (const float*)d_in[9];
    const float*  rvar  = (const float*)d_in[10];
    float* out = (float*)d_out;

    probe_kernel<<<1, 1>>>();   // shifts ncu -s 5 onto point_mma_kernel
    zero_hist_kernel<<<NBKT / 256, 256>>>();
    pass_a_kernel<<<TOTAL_PTS / 256, 256>>>(pts);
    scan_kernel<<<1, 1024>>>();
    pass_b_kernel<<<TOTAL_PTS / 256, 256>>>();

    cudaFuncSetAttribute(point_mma_kernel,
                         cudaFuncAttributeMaxDynamicSharedMemorySize, SM_TOTAL);
    point_mma_kernel<<<MLP_CTAS, 128, SM_TOTAL>>>(pts, W1, b1, W2, b2);
    bev_mma_kernel<<<BEV_GRID, 128>>>(Wp, bp, gamma, beta, rmean, rvar, out);
}

// round 12
// speedup vs baseline: 1.8102x; 1.8102x over previous
#include <cuda_runtime.h>
#include <cstdint>

#define BEV_H 128
#define BEV_W 128
#define HW_ (BEV_H * BEV_W)
#define NBKT (4 * HW_)            // 65536 buckets
#define C_MID 80
#define C_OUT 128
#define B_ 4
#define NP_ 200000
#define TOTAL_PTS (B_ * NP_)
#define INVALID_G 0xFFFFFFFFu

#define MLP_CTAS 1184
#define MLP_WARPS (MLP_CTAS * 4)

#define BEV_TILES (B_ * HW_ / 16)
#define BEV_TPW 4
#define BEV_GRID (BEV_TILES / (4 * BEV_TPW))   // 256

// Scratch (device globals; zero-init at load, re-zeroed per launch as noted).
__device__ float g_sums[(size_t)B_ * HW_ * C_MID];  // zeroed by bev kernel
__device__ int h_cnt[NBKT];                          // zeroed by zero kernel
__device__ int g_off[NBKT + 1];                      // rewritten by scan
__device__ int g_blk[256];                           // block totals for scan
__device__ unsigned g_bkt[TOTAL_PTS];                // rewritten by pass A
__device__ unsigned g_ids[TOTAL_PTS];                // written by pass B

// ---------------------------------------------------------------------------
// helpers
// ---------------------------------------------------------------------------
__device__ __forceinline__ uint32_t f2tf32(float x) {
    uint32_t u;
    asm("cvt.rna.tf32.f32 %0, %1;" : "=r"(u) : "f"(x));
    return u;
}
__device__ __forceinline__ uint32_t packh2(float lo, float hi) {
    uint32_t r;
    asm("cvt.rn.f16x2.f32 %0, %1, %2;" : "=r"(r) : "f"(hi), "f"(lo));
    return r;
}
__device__ __forceinline__ void mma_f16(float* c, const uint32_t* a,
                                        uint32_t b0, uint32_t b1) {
    asm("mma.sync.aligned.m16n8k16.row.col.f32.f16.f16.f32 "
        "{%0,%1,%2,%3}, {%4,%5,%6,%7}, {%8,%9}, {%0,%1,%2,%3};"
        : "+f"(c[0]), "+f"(c[1]), "+f"(c[2]), "+f"(c[3])
        : "r"(a[0]), "r"(a[1]), "r"(a[2]), "r"(a[3]), "r"(b0), "r"(b1));
}
__device__ __forceinline__ void mma_tf32(float* c, const uint32_t* a,
                                         uint32_t b0, uint32_t b1) {
    asm("mma.sync.aligned.m16n8k8.row.col.f32.tf32.tf32.f32 "
        "{%0,%1,%2,%3}, {%4,%5,%6,%7}, {%8,%9}, {%0,%1,%2,%3};"
        : "+f"(c[0]), "+f"(c[1]), "+f"(c[2]), "+f"(c[3])
        : "r"(a[0]), "r"(a[1]), "r"(a[2]), "r"(a[3]), "r"(b0), "r"(b1));
}
__device__ __forceinline__ void red_v4(float* addr, float4 v) {
    asm volatile("red.global.add.v4.f32 [%0], {%1, %2, %3, %4};"
                 :: "l"(addr), "f"(v.x), "f"(v.y), "f"(v.z), "f"(v.w) : "memory");
}

// ---------------------------------------------------------------------------
// Pipeline kernels
// ---------------------------------------------------------------------------
__global__ void zero_hist_kernel() {
    int i = blockIdx.x * 256 + threadIdx.x;
    if (i < NBKT) h_cnt[i] = 0;
}

__global__ __launch_bounds__(256)
void pass_a_kernel(const float4* __restrict__ pts) {
    int i = blockIdx.x * 256 + threadIdx.x;
    float4 p = pts[i];
    int ix = (int)floorf((p.x + 50.0f) / 0.78125f);
    int iy = (int)floorf((p.y + 50.0f) / 0.78125f);
    bool v = (ix >= 0) & (ix < BEV_W) & (iy >= 0) & (iy < BEV_H);
    unsigned g = v ? (unsigned)((i / NP_) * HW_ + iy * BEV_W + ix) : INVALID_G;
    g_bkt[i] = g;
    if (v) atomicAdd(&h_cnt[g], 1);
}

// Blocked scan: 256 CTAs local scan -> 1 CTA scans block totals -> add back.
__global__ __launch_bounds__(256)
void scan1_kernel() {
    __shared__ int s[256];
    const int t = threadIdx.x, i = blockIdx.x * 256 + t;
    int c = h_cnt[i];
    s[t] = c; __syncthreads();
    int x = c;
#pragma unroll
    for (int d = 1; d < 256; d <<= 1) {
        int y = (t >= d) ? s[t - d] : 0;
        __syncthreads();
        x += y; s[t] = x;
        __syncthreads();
    }
    g_off[i] = x - c;                       // local exclusive
    if (t == 255) g_blk[blockIdx.x] = x;    // block total
}

__global__ __launch_bounds__(256)
void scan2_kernel() {
    __shared__ int s[256];
    const int t = threadIdx.x;
    int c = g_blk[t];
    s[t] = c; __syncthreads();
    int x = c;
#pragma unroll
    for (int d = 1; d < 256; d <<= 1) {
        int y = (t >= d) ? s[t - d] : 0;
        __syncthreads();
        x += y; s[t] = x;
        __syncthreads();
    }
    g_blk[t] = x - c;                       // exclusive block offsets
    if (t == 255) g_off[NBKT] = x;          // grand total (valid points)
}

__global__ __launch_bounds__(256)
void scan3_kernel() {
    const int i = blockIdx.x * 256 + threadIdx.x;
    g_off[i] += g_blk[blockIdx.x];
}

__global__ __launch_bounds__(256)
void pass_b_kernel() {
    int i = blockIdx.x * 256 + threadIdx.x;
    unsigned g = g_bkt[i];
    if (g != INVALID_G) {
        int pos = atomicAdd(&g_off[g], 1);
        g_ids[pos] = (unsigned)i;
    }
}

// ---------------------------------------------------------------------------
// MLP kernel: sorted points, both layers on tensor cores, segmented scatter.
// ---------------------------------------------------------------------------
#define SM_W2F   0            // 12800 B
#define SM_W1F   12800        // 2560 B
#define SM_B2    15360        // 320 B
#define SM_SBKT  15680        // 512 B (4 warps * 32 int)
#define SM_BUF   16192        // 40960 B (4 warps * 32*80 f32)
#define SM_TOTAL 57152

__global__ __launch_bounds__(128, 4)
void point_mma_kernel(const float4* __restrict__ pts,
                      const float* __restrict__ W1, const float* __restrict__ b1,
                      const float* __restrict__ W2, const float* __restrict__ b2) {
    extern __shared__ __align__(16) char smem[];
    uint32_t* sW2F = (uint32_t*)(smem + SM_W2F);
    uint32_t* sW1F = (uint32_t*)(smem + SM_W1F);
    float*    sb2  = (float*)(smem + SM_B2);
    int*      sbktA = (int*)(smem + SM_SBKT);

    const int tid = threadIdx.x;
    const int w = tid >> 5;
    const int lane = tid & 31;
    const int qg = lane >> 2;
    const int tig = lane & 3;
    int*   sbkt = sbktA + w * 32;
    float* buf  = (float*)(smem + SM_BUF) + w * 32 * C_MID;

    for (int i = tid; i < C_MID; i += 128) sb2[i] = b2[i];
    for (int e = tid; e < 3200; e += 128) {
        int reg = e & 1;
        int L = (e >> 1) & 31;
        int idx = e >> 6;
        int ns = idx % 10, ks = idx / 10;
        int k0 = ks * 16 + 2 * (L & 3) + reg * 8;
        int n = ns * 8 + (L >> 2);
        sW2F[e] = packh2(W2[k0 * C_MID + n], W2[(k0 + 1) * C_MID + n]);
    }
    for (int e = tid; e < 640; e += 128) {
        int pair = e & 1;
        int L = (e >> 1) & 31;
        int ns = e >> 6;
        int tg = L & 3;
        int n = ns * 8 + (L >> 2);
        float v;
        if (pair == 0) v = W1[tg * C_MID + n];
        else           v = (tg == 0) ? b1[n] : W1[(tg - 1) * C_MID + n];
        sW1F[e] = f2tf32(v);
    }
    __syncthreads();

    float4 bias4 = make_float4(0.f, 0.f, 0.f, 0.f);
    if (lane < 20) bias4 = *reinterpret_cast<const float4*>(&sb2[4 * lane]);

    const int valid = g_off[NBKT];
    const int ntiles = (valid + 31) >> 5;
    const int gwarp = blockIdx.x * 4 + w;

#pragma unroll 1
    for (int tile = gwarp; tile < ntiles; tile += MLP_WARPS) {
        const int base = tile * 32;

        float4 P[4];
        int ids[4];
        bool vr[4];
#pragma unroll
        for (int j = 0; j < 4; j++) {
            int r = base + qg + 8 * j;
            bool ok = r < valid;
            int id = ok ? (int)g_ids[r] : 0;
            ids[j] = id; vr[j] = ok;
            P[j] = pts[id];
        }

        {
            int myg = -1;
            if (vr[tig]) {
                float4 po = P[tig];
                int ixo = (int)floorf((po.x + 50.0f) / 0.78125f);
                int iyo = (int)floorf((po.y + 50.0f) / 0.78125f);
                myg = (ids[tig] / NP_) * HW_ + iyo * BEV_W + ixo;
            }
            sbkt[qg + 8 * tig] = myg;
        }
        __syncwarp();

        uint32_t ALo[4], AHi[4];
#pragma unroll
        for (int j = 0; j < 4; j++) {
            float4 p = P[j];
            float ch = (tig == 0) ? p.x : (tig == 1) ? p.y : (tig == 2) ? p.z : p.w;
            uint32_t ahi = f2tf32(ch);
            float cl = (tig == 1) ? p.x : (tig == 2) ? p.y : p.z;
            float lo = cl - __uint_as_float(f2tf32(cl));
            uint32_t alo = (tig == 0) ? 0x3f800000u : f2tf32(lo);
            if (j < 2) { ALo[j] = ahi; ALo[2 + j] = alo; }
            else       { AHi[j - 2] = ahi; AHi[j] = alo; }
        }

        uint32_t A0[5][4], A1[5][4];
#pragma unroll
        for (int ns = 0; ns < 10; ns++) {
            uint2 bf = *reinterpret_cast<const uint2*>(&sW1F[(ns * 32 + lane) * 2]);
            float cL[4] = {0.f, 0.f, 0.f, 0.f};
            float cH[4] = {0.f, 0.f, 0.f, 0.f};
            mma_tf32(cL, ALo, bf.x, bf.y);
            mma_tf32(cH, AHi, bf.x, bf.y);
            const int ks = ns >> 1, sub = ns & 1;
            A0[ks][2 * sub + 0] = packh2(fmaxf(cL[0], 0.f), fmaxf(cL[1], 0.f));
            A0[ks][2 * sub + 1] = packh2(fmaxf(cL[2], 0.f), fmaxf(cL[3], 0.f));
            A1[ks][2 * sub + 0] = packh2(fmaxf(cH[0], 0.f), fmaxf(cH[1], 0.f));
            A1[ks][2 * sub + 1] = packh2(fmaxf(cH[2], 0.f), fmaxf(cH[3], 0.f));
        }

#pragma unroll 1
        for (int ns = 0; ns < 10; ns++) {
            float c0[4] = {0.f, 0.f, 0.f, 0.f};
            float c1[4] = {0.f, 0.f, 0.f, 0.f};
#pragma unroll
            for (int ks = 0; ks < 5; ks++) {
                uint2 bf = *reinterpret_cast<const uint2*>(
                    &sW2F[((ks * 10 + ns) * 32 + lane) * 2]);
                mma_f16(c0, A0[ks], bf.x, bf.y);
                mma_f16(c1, A1[ks], bf.x, bf.y);
            }
            const int col = ns * 8 + 2 * tig;
            *reinterpret_cast<float2*>(&buf[qg * C_MID + col])        = make_float2(c0[0], c0[1]);
            *reinterpret_cast<float2*>(&buf[(qg + 8) * C_MID + col])  = make_float2(c0[2], c0[3]);
            *reinterpret_cast<float2*>(&buf[(qg + 16) * C_MID + col]) = make_float2(c1[0], c1[1]);
            *reinterpret_cast<float2*>(&buf[(qg + 24) * C_MID + col]) = make_float2(c1[2], c1[3]);
        }
        __syncwarp();

        // Segmented reduction over sorted rows; one red.v4 per segment.
        int cur = -1;
        float4 acc = make_float4(0.f, 0.f, 0.f, 0.f);
#pragma unroll 1
        for (int r = 0; r < 32; r++) {
            int bk = sbkt[r];
            float4 v = make_float4(0.f, 0.f, 0.f, 0.f);
            if (lane < 20) v = *reinterpret_cast<const float4*>(&buf[r * C_MID + 4 * lane]);
            v.x = fmaxf(v.x + bias4.x, 0.0f);
            v.y = fmaxf(v.y + bias4.y, 0.0f);
            v.z = fmaxf(v.z + bias4.z, 0.0f);
            v.w = fmaxf(v.w + bias4.w, 0.0f);
            if (bk != cur) {
                if (cur >= 0 && lane < 20)
                    red_v4(&g_sums[(size_t)cur * C_MID + 4 * lane], acc);
                cur = bk;
                acc = v;
            } else {
                acc.x += v.x; acc.y += v.y; acc.z += v.z; acc.w += v.w;
            }
        }
        if (cur >= 0 && lane < 20)
            red_v4(&g_sums[(size_t)cur * C_MID + 4 * lane], acc);
        __syncwarp();
    }
}

// ---------------------------------------------------------------------------
// bev kernel: mean + 1x1 conv + BN + relu via tensor cores.
// ---------------------------------------------------------------------------
__global__ __launch_bounds__(128)
void bev_mma_kernel(const float* __restrict__ Wp, const float* __restrict__ bp,
                    const float* __restrict__ gamma, const float* __restrict__ beta,
                    const float* __restrict__ rmean, const float* __restrict__ rvar,
                    float* __restrict__ out) {
    __shared__ uint32_t sWpF[10 * 16 * 32 * 2];  // 40 KB
    __shared__ float sScale[C_OUT];
    __shared__ float sShift[C_OUT];

    const int tid = threadIdx.x;
    const int w = tid >> 5;
    const int lane = tid & 31;
    const int qg = lane >> 2;
    const int tig = lane & 3;

    for (int e = tid; e < 10240; e += 128) {
        int pair = e & 1;
        int L = (e >> 1) & 31;
        int idx = e >> 6;
        int ns = idx & 15, ks = idx >> 4;
        int k = ks * 8 + (L & 3) + pair * 4;
        int n = ns * 8 + (L >> 2);
        sWpF[e] = f2tf32(Wp[k * C_OUT + n]);
    }
    if (tid < C_OUT) {
        float sc = gamma[tid] * rsqrtf(rvar[tid] + 1e-5f);
        sScale[tid] = sc;
        sShift[tid] = beta[tid] + (bp[tid] - rmean[tid]) * sc;
    }
    __syncthreads();

#pragma unroll 1
    for (int t = 0; t < BEV_TPW; t++) {
        const int tile = (blockIdx.x * 4 + w) * BEV_TPW + t;
        const int tb = tile * 16;

        float inv0 = 1.0f / fmaxf((float)h_cnt[tb + qg], 1.0f);
        float inv1 = 1.0f / fmaxf((float)h_cnt[tb + qg + 8], 1.0f);
        const float* p0 = &g_sums[(size_t)(tb + qg) * C_MID];
        const float* p1 = &g_sums[(size_t)(tb + qg + 8) * C_MID];

        uint32_t A[10][4];
#pragma unroll
        for (int ks = 0; ks < 10; ks++) {
            const int c0 = ks * 8 + tig, c1 = c0 + 4;
            A[ks][0] = f2tf32(p0[c0] * inv0);
            A[ks][1] = f2tf32(p1[c0] * inv1);
            A[ks][2] = f2tf32(p0[c1] * inv0);
            A[ks][3] = f2tf32(p1[c1] * inv1);
        }
        __syncwarp();
        float4* zs = reinterpret_cast<float4*>(&g_sums[(size_t)tb * C_MID]);
#pragma unroll
        for (int j = 0; j < 10; j++)
            zs[lane + 32 * j] = make_float4(0.f, 0.f, 0.f, 0.f);

        const int b = tb / HW_;
        const int rem = tb % HW_;
        float* outb = out + (size_t)b * C_OUT * HW_ + rem;

#pragma unroll 1
        for (int ns = 0; ns < 16; ns++) {
            float c[4] = {0.f, 0.f, 0.f, 0.f};
#pragma unroll
            for (int ks = 0; ks < 10; ks++) {
                uint2 bf = *reinterpret_cast<const uint2*>(
                    &sWpF[((ks * 16 + ns) * 32 + lane) * 2]);
                mma_tf32(c, A[ks], bf.x, bf.y);
            }
            const int col0 = ns * 8 + 2 * tig;
            float2 sc = *reinterpret_cast<const float2*>(&sScale[col0]);
            float2 sh = *reinterpret_cast<const float2*>(&sShift[col0]);
            outb[(size_t)col0 * HW_ + qg]           = fmaxf(fmaf(c[0], sc.x, sh.x), 0.0f);
            outb[(size_t)(col0 + 1) * HW_ + qg]     = fmaxf(fmaf(c[1], sc.y, sh.y), 0.0f);
            outb[(size_t)col0 * HW_ + qg + 8]       = fmaxf(fmaf(c[2], sc.x, sh.x), 0.0f);
            outb[(size_t)(col0 + 1) * HW_ + qg + 8] = fmaxf(fmaf(c[3], sc.y, sh.y), 0.0f);
        }
        __syncwarp();
    }
}

__global__ void probe_kernel() {}

// ---------------------------------------------------------------------------
extern "C" void kernel_launch(void* const* d_in, const int* in_sizes, int n_in,
                              void* d_out, int out_size) {
    const float4* pts   = (const float4*)d_in[0];
    const float*  W1    = (const float*)d_in[1];
    const float*  b1    = (const float*)d_in[2];
    const float*  W2    = (const float*)d_in[3];
    const float*  b2    = (const float*)d_in[4];
    const float*  Wp    = (const float*)d_in[5];
    const float*  bp    = (const float*)d_in[6];
    const float*  gamma = (const float*)d_in[7];
    const float*  beta  = (const float*)d_in[8];
    const float*  rmean = (const float*)d_in[9];
    const float*  rvar  = (const float*)d_in[10];
    float* out = (float*)d_out;

    zero_hist_kernel<<<NBKT / 256, 256>>>();
    pass_a_kernel<<<TOTAL_PTS / 256, 256>>>(pts);
    scan1_kernel<<<256, 256>>>();
    scan2_kernel<<<1, 256>>>();
    scan3_kernel<<<256, 256>>>();
    pass_b_kernel<<<TOTAL_PTS / 256, 256>>>();

    cudaFuncSetAttribute(point_mma_kernel,
                         cudaFuncAttributeMaxDynamicSharedMemorySize, SM_TOTAL);
    point_mma_kernel<<<MLP_CTAS, 128, SM_TOTAL>>>(pts, W1, b1, W2, b2);
    bev_mma_kernel<<<BEV_GRID, 128>>>(Wp, bp, gamma, beta, rmean, rvar, out);
    probe_kernel<<<1, 1>>>();
}

// round 13
// speedup vs baseline: 2.1045x; 1.1625x over previous
#include <cuda_runtime.h>
#include <cstdint>

#define BEV_H 128
#define BEV_W 128
#define HW_ (BEV_H * BEV_W)
#define NBKT (4 * HW_)
#define C_MID 80
#define C_OUT 128
#define B_ 4
#define NP_ 200000
#define TOTAL_PTS (B_ * NP_)

#define MLP_CTAS 1184
#define MLP_WARPS (MLP_CTAS * 4)

#define BEV_TILES (B_ * HW_ / 16)
#define BEV_TPW 4
#define BEV_GRID (BEV_TILES / (4 * BEV_TPW))   // 256

// Device-global scratch. h_cnt zeroed by bev kernel (zero-init at load);
// g_off/g_blk/g_bkt/g_ids fully rewritten every iteration; g_sums zeroed by bev.
__device__ float g_sums[(size_t)B_ * HW_ * C_MID];
__device__ int h_cnt[NBKT];
__device__ int g_off[NBKT + 1];
__device__ int g_blk[256];
__device__ unsigned g_bkt[TOTAL_PTS];
__device__ unsigned g_ids[TOTAL_PTS];

// ---------------------------------------------------------------------------
__device__ __forceinline__ uint32_t f2tf32(float x) {
    uint32_t u;
    asm("cvt.rna.tf32.f32 %0, %1;" : "=r"(u) : "f"(x));
    return u;
}
__device__ __forceinline__ uint32_t packh2(float lo, float hi) {
    uint32_t r;
    asm("cvt.rn.f16x2.f32 %0, %1, %2;" : "=r"(r) : "f"(hi), "f"(lo));
    return r;
}
__device__ __forceinline__ void mma_f16(float* c, const uint32_t* a,
                                        uint32_t b0, uint32_t b1) {
    asm("mma.sync.aligned.m16n8k16.row.col.f32.f16.f16.f32 "
        "{%0,%1,%2,%3}, {%4,%5,%6,%7}, {%8,%9}, {%0,%1,%2,%3};"
        : "+f"(c[0]), "+f"(c[1]), "+f"(c[2]), "+f"(c[3])
        : "r"(a[0]), "r"(a[1]), "r"(a[2]), "r"(a[3]), "r"(b0), "r"(b1));
}
__device__ __forceinline__ void mma_tf32(float* c, const uint32_t* a,
                                         uint32_t b0, uint32_t b1) {
    asm("mma.sync.aligned.m16n8k8.row.col.f32.tf32.tf32.f32 "
        "{%0,%1,%2,%3}, {%4,%5,%6,%7}, {%8,%9}, {%0,%1,%2,%3};"
        : "+f"(c[0]), "+f"(c[1]), "+f"(c[2]), "+f"(c[3])
        : "r"(a[0]), "r"(a[1]), "r"(a[2]), "r"(a[3]), "r"(b0), "r"(b1));
}
__device__ __forceinline__ void red_v2(float* addr, float a, float b) {
    asm volatile("red.global.add.v2.f32 [%0], {%1, %2};"
                 :: "l"(addr), "f"(a), "f"(b) : "memory");
}

// ---------------------------------------------------------------------------
// Pre-pass kernels
// ---------------------------------------------------------------------------
__global__ __launch_bounds__(256)
void pass_a_kernel(const float4* __restrict__ pts) {
    int i = blockIdx.x * 256 + threadIdx.x;
    float4 p = pts[i];
    int ix = (int)floorf((p.x + 50.0f) / 0.78125f);
    int iy = (int)floorf((p.y + 50.0f) / 0.78125f);
    bool v = (ix >= 0) & (ix < BEV_W) & (iy >= 0) & (iy < BEV_H);
    unsigned g = v ? (unsigned)((i / NP_) * HW_ + iy * BEV_W + ix) : 0xFFFFFFFFu;
    g_bkt[i] = g;
    if (v) atomicAdd(&h_cnt[g], 1);
}

__global__ __launch_bounds__(256)
void scan1_kernel() {
    __shared__ int s[256];
    const int t = threadIdx.x, i = blockIdx.x * 256 + t;
    int c = h_cnt[i];
    s[t] = c; __syncthreads();
    int x = c;
#pragma unroll
    for (int d = 1; d < 256; d <<= 1) {
        int y = (t >= d) ? s[t - d] : 0;
        __syncthreads();
        x += y; s[t] = x;
        __syncthreads();
    }
    g_off[i] = x - c;
    if (t == 255) g_blk[blockIdx.x] = x;
}

// Fused scan2+scan3: every CTA redundantly scans the 256 block totals,
// then adds its block's exclusive offset to its 256 g_off entries.
__global__ __launch_bounds__(256)
void scan23_kernel() {
    __shared__ int s[256];
    const int t = threadIdx.x;
    int c = g_blk[t];
    s[t] = c; __syncthreads();
    int x = c;
#pragma unroll
    for (int d = 1; d < 256; d <<= 1) {
        int y = (t >= d) ? s[t - d] : 0;
        __syncthreads();
        x += y; s[t] = x;
        __syncthreads();
    }
    // s[k] now inclusive prefix
    int off = (blockIdx.x == 0) ? 0 : s[blockIdx.x - 1];
    g_off[blockIdx.x * 256 + t] += off;
    if (blockIdx.x == 255 && t == 255) g_off[NBKT] = s[255];
}

__global__ __launch_bounds__(256)
void pass_b_kernel() {
    int i = blockIdx.x * 256 + threadIdx.x;
    unsigned g = g_bkt[i];
    if (g != 0xFFFFFFFFu) {
        int pos = atomicAdd(&g_off[g], 1);
        g_ids[pos] = (unsigned)i;
    }
}

// ---------------------------------------------------------------------------
// MLP kernel: sorted points; tile row r <- sorted point base + 4*(r&7)+(r>>3),
// so each lane's 4 C-fragment rows are 4 CONSECUTIVE sorted points. Segmented
// reduction happens in registers; ~1.3 predicated red.v2 per lane per ns.
// ---------------------------------------------------------------------------
__global__ __launch_bounds__(128, 5)
void point_mma_kernel(const float4* __restrict__ pts,
                      const float* __restrict__ W1, const float* __restrict__ b1,
                      const float* __restrict__ W2, const float* __restrict__ b2) {
    __shared__ uint32_t sW2F[5 * 10 * 32 * 2];   // 12.8 KB
    __shared__ uint32_t sW1F[10 * 32 * 2];       // 2.5 KB
    __shared__ __align__(8) float sb2[C_MID];

    const int tid = threadIdx.x;
    const int w = tid >> 5;
    const int lane = tid & 31;
    const int qg = lane >> 2;
    const int tig = lane & 3;

    for (int i = tid; i < C_MID; i += 128) sb2[i] = b2[i];
    for (int e = tid; e < 3200; e += 128) {
        int reg = e & 1;
        int L = (e >> 1) & 31;
        int idx = e >> 6;
        int ns = idx % 10, ks = idx / 10;
        int k0 = ks * 16 + 2 * (L & 3) + reg * 8;
        int n = ns * 8 + (L >> 2);
        sW2F[e] = packh2(W2[k0 * C_MID + n], W2[(k0 + 1) * C_MID + n]);
    }
    for (int e = tid; e < 640; e += 128) {
        int pair = e & 1;
        int L = (e >> 1) & 31;
        int ns = e >> 6;
        int tg = L & 3;
        int n = ns * 8 + (L >> 2);
        float v;
        if (pair == 0) v = W1[tg * C_MID + n];
        else           v = (tg == 0) ? b1[n] : W1[(tg - 1) * C_MID + n];
        sW1F[e] = f2tf32(v);
    }
    __syncthreads();

    const int valid = g_off[NBKT];
    const int ntiles = (valid + 31) >> 5;
    const int gwarp = blockIdx.x * 4 + w;

#pragma unroll 1
    for (int tile = gwarp; tile < ntiles; tile += MLP_WARPS) {
        const int s0 = tile * 32 + 4 * qg;   // this lane's 4 consecutive pts

        // Gather 4 consecutive sorted points + compute their buckets.
        float4 P[4];
        int bk[4];
#pragma unroll
        for (int j = 0; j < 4; j++) {
            int r = s0 + j;
            bool ok = r < valid;
            int id = ok ? (int)g_ids[r] : 0;
            P[j] = pts[id];
            int ix = (int)floorf((P[j].x + 50.0f) / 0.78125f);
            int iy = (int)floorf((P[j].y + 50.0f) / 0.78125f);
            bk[j] = ok ? ((id / NP_) * HW_ + iy * BEV_W + ix) : -1;
        }
        const bool m01 = (bk[0] == bk[1]);
        const bool m12 = (bk[1] == bk[2]);
        const bool m23 = (bk[2] == bk[3]);

        // Layer-1 A fragments (split tf32, exact). Row qg+8j holds P[j].
        uint32_t ALo[4], AHi[4];
#pragma unroll
        for (int j = 0; j < 4; j++) {
            float4 p = P[j];
            float ch = (tig == 0) ? p.x : (tig == 1) ? p.y : (tig == 2) ? p.z : p.w;
            uint32_t ahi = f2tf32(ch);
            float cl = (tig == 1) ? p.x : (tig == 2) ? p.y : p.z;
            float lo = cl - __uint_as_float(f2tf32(cl));
            uint32_t alo = (tig == 0) ? 0x3f800000u : f2tf32(lo);
            if (j < 2) { ALo[j] = ahi; ALo[2 + j] = alo; }
            else       { AHi[j - 2] = ahi; AHi[j] = alo; }
        }

        // Layer 1 via mma -> fp16 layer-2 A fragments.
        uint32_t A0[5][4], A1[5][4];
#pragma unroll
        for (int ns = 0; ns < 10; ns++) {
            uint2 bf = *reinterpret_cast<const uint2*>(&sW1F[(ns * 32 + lane) * 2]);
            float cL[4] = {0.f, 0.f, 0.f, 0.f};
            float cH[4] = {0.f, 0.f, 0.f, 0.f};
            mma_tf32(cL, ALo, bf.x, bf.y);
            mma_tf32(cH, AHi, bf.x, bf.y);
            const int ks = ns >> 1, sub = ns & 1;
            A0[ks][2 * sub + 0] = packh2(fmaxf(cL[0], 0.f), fmaxf(cL[1], 0.f));
            A0[ks][2 * sub + 1] = packh2(fmaxf(cL[2], 0.f), fmaxf(cL[3], 0.f));
            A1[ks][2 * sub + 0] = packh2(fmaxf(cH[0], 0.f), fmaxf(cH[1], 0.f));
            A1[ks][2 * sub + 1] = packh2(fmaxf(cH[2], 0.f), fmaxf(cH[3], 0.f));
        }

        // Layer 2 + in-register segmented scatter.
#pragma unroll 1
        for (int ns = 0; ns < 10; ns++) {
            float c0[4] = {0.f, 0.f, 0.f, 0.f};
            float c1[4] = {0.f, 0.f, 0.f, 0.f};
#pragma unroll
            for (int ks = 0; ks < 5; ks++) {
                uint2 bf = *reinterpret_cast<const uint2*>(
                    &sW2F[((ks * 10 + ns) * 32 + lane) * 2]);
                mma_f16(c0, A0[ks], bf.x, bf.y);
                mma_f16(c1, A1[ks], bf.x, bf.y);
            }
            const int col = ns * 8 + 2 * tig;
            float2 bb = *reinterpret_cast<const float2*>(&sb2[col]);
            // point j values (bias+relu per point BEFORE summation):
            float v0x = fmaxf(c0[0] + bb.x, 0.f), v0y = fmaxf(c0[1] + bb.y, 0.f);
            float v1x = fmaxf(c0[2] + bb.x, 0.f), v1y = fmaxf(c0[3] + bb.y, 0.f);
            float v2x = fmaxf(c1[0] + bb.x, 0.f), v2y = fmaxf(c1[1] + bb.y, 0.f);
            float v3x = fmaxf(c1[2] + bb.x, 0.f), v3y = fmaxf(c1[3] + bb.y, 0.f);
            // backward merge of equal adjacent buckets (sorted => contiguous)
            if (m23) { v2x += v3x; v2y += v3y; }
            if (m12) { v1x += v2x; v1y += v2y; }
            if (m01) { v0x += v1x; v0y += v1y; }
            if (bk[0] >= 0)
                red_v2(&g_sums[(size_t)bk[0] * C_MID + col], v0x, v0y);
            if (bk[1] >= 0 && !m01)
                red_v2(&g_sums[(size_t)bk[1] * C_MID + col], v1x, v1y);
            if (bk[2] >= 0 && !m12)
                red_v2(&g_sums[(size_t)bk[2] * C_MID + col], v2x, v2y);
            if (bk[3] >= 0 && !m23)
                red_v2(&g_sums[(size_t)bk[3] * C_MID + col], v3x, v3y);
        }
    }
}

// ---------------------------------------------------------------------------
// bev kernel: mean + 1x1 conv + BN + relu via tensor cores.
// Zeroes g_sums AND h_cnt behind the reads (regions are warp-private).
// ---------------------------------------------------------------------------
__global__ __launch_bounds__(128)
void bev_mma_kernel(const float* __restrict__ Wp, const float* __restrict__ bp,
                    const float* __restrict__ gamma, const float* __restrict__ beta,
                    const float* __restrict__ rmean, const float* __restrict__ rvar,
                    float* __restrict__ out) {
    __shared__ uint32_t sWpF[10 * 16 * 32 * 2];  // 40 KB
    __shared__ float sScale[C_OUT];
    __shared__ float sShift[C_OUT];

    const int tid = threadIdx.x;
    const int w = tid >> 5;
    const int lane = tid & 31;
    const int qg = lane >> 2;
    const int tig = lane & 3;

    for (int e = tid; e < 10240; e += 128) {
        int pair = e & 1;
        int L = (e >> 1) & 31;
        int idx = e >> 6;
        int ns = idx & 15, ks = idx >> 4;
        int k = ks * 8 + (L & 3) + pair * 4;
        int n = ns * 8 + (L >> 2);
        sWpF[e] = f2tf32(Wp[k * C_OUT + n]);
    }
    if (tid < C_OUT) {
        float sc = gamma[tid] * rsqrtf(rvar[tid] + 1e-5f);
        sScale[tid] = sc;
        sShift[tid] = beta[tid] + (bp[tid] - rmean[tid]) * sc;
    }
    __syncthreads();

#pragma unroll 1
    for (int t = 0; t < BEV_TPW; t++) {
        const int tile = (blockIdx.x * 4 + w) * BEV_TPW + t;
        const int tb = tile * 16;

        float inv0 = 1.0f / fmaxf((float)h_cnt[tb + qg], 1.0f);
        float inv1 = 1.0f / fmaxf((float)h_cnt[tb + qg + 8], 1.0f);
        const float* p0 = &g_sums[(size_t)(tb + qg) * C_MID];
        const float* p1 = &g_sums[(size_t)(tb + qg + 8) * C_MID];

        uint32_t A[10][4];
#pragma unroll
        for (int ks = 0; ks < 10; ks++) {
            const int c0 = ks * 8 + tig, c1 = c0 + 4;
            A[ks][0] = f2tf32(p0[c0] * inv0);
            A[ks][1] = f2tf32(p1[c0] * inv1);
            A[ks][2] = f2tf32(p0[c1] * inv0);
            A[ks][3] = f2tf32(p1[c1] * inv1);
        }
        __syncwarp();
        float4* zs = reinterpret_cast<float4*>(&g_sums[(size_t)tb * C_MID]);
#pragma unroll
        for (int j = 0; j < 10; j++)
            zs[lane + 32 * j] = make_float4(0.f, 0.f, 0.f, 0.f);
        if (lane < 16) h_cnt[tb + lane] = 0;

        const int b = tb / HW_;
        const int rem = tb % HW_;
        float* outb = out + (size_t)b * C_OUT * HW_ + rem;

#pragma unroll 1
        for (int ns = 0; ns < 16; ns++) {
            float c[4] = {0.f, 0.f, 0.f, 0.f};
#pragma unroll
            for (int ks = 0; ks < 10; ks++) {
                uint2 bf = *reinterpret_cast<const uint2*>(
                    &sWpF[((ks * 16 + ns) * 32 + lane) * 2]);
                mma_tf32(c, A[ks], bf.x, bf.y);
            }
            const int col0 = ns * 8 + 2 * tig;
            float2 sc = *reinterpret_cast<const float2*>(&sScale[col0]);
            float2 sh = *reinterpret_cast<const float2*>(&sShift[col0]);
            outb[(size_t)col0 * HW_ + qg]           = fmaxf(fmaf(c[0], sc.x, sh.x), 0.0f);
            outb[(size_t)(col0 + 1) * HW_ + qg]     = fmaxf(fmaf(c[1], sc.y, sh.y), 0.0f);
            outb[(size_t)col0 * HW_ + qg + 8]       = fmaxf(fmaf(c[2], sc.x, sh.x), 0.0f);
            outb[(size_t)(col0 + 1) * HW_ + qg + 8] = fmaxf(fmaf(c[3], sc.y, sh.y), 0.0f);
        }
        __syncwarp();
    }
}

__global__ void probe_kernel() {}

// ---------------------------------------------------------------------------
extern "C" void kernel_launch(void* const* d_in, const int* in_sizes, int n_in,
                              void* d_out, int out_size) {
    const float4* pts   = (const float4*)d_in[0];
    const float*  W1    = (const float*)d_in[1];
    const float*  b1    = (const float*)d_in[2];
    const float*  W2    = (const float*)d_in[3];
    const float*  b2    = (const float*)d_in[4];
    const float*  Wp    = (const float*)d_in[5];
    const float*  bp    = (const float*)d_in[6];
    const float*  gamma = (const float*)d_in[7];
    const float*  beta  = (const float*)d_in[8];
    const float*  rmean = (const float*)d_in[9];
    const float*  rvar  = (const float*)d_in[10];
    float* out = (float*)d_out;

    probe_kernel<<<1, 1>>>();              // ncu -s 5 lands on point_mma_kernel
    pass_a_kernel<<<TOTAL_PTS / 256, 256>>>(pts);
    scan1_kernel<<<256, 256>>>();
    scan23_kernel<<<256, 256>>>();
    pass_b_kernel<<<TOTAL_PTS / 256, 256>>>();
    point_mma_kernel<<<MLP_CTAS, 128>>>(pts, W1, b1, W2, b2);
    bev_mma_kernel<<<BEV_GRID, 128>>>(Wp, bp, gamma, beta, rmean, rvar, out);
}